// round 8
// baseline (speedup 1.0000x reference)
#include <cuda_runtime.h>
#include <cuda_bf16.h>

// EdgeDecoder: per-edge bilinear scores over 5 relations + softmax-expected rating.
//   z_user  [100000, 64] f32
//   z_movie [ 50000, 64] f32
//   rel_emb [     5, 64] f32
//   edge_label_index [2, E] int (32 or 64 — detected at runtime)
//   out [E] f32
//
// R8 = R7 (best: 53.6us) + SINGLE-WAVE GRID:
//   R7 launched 1216 CTAs into 760 resident slots (152 SM x 5 CTA @ 48 regs)
//   = 1.6 waves -> wave-2 drain left 40% of the chip idle for half the run
//   (80% utilization, matching occ 52% vs configured 62.5%). Launch exactly
//   760 CTAs: one balanced wave, ~41 edges per 8-lane group.
// Retained: smem relD (softmax shift trick), 2-edge unroll (4 in-flight
// 128B gathers/warp), line-aligned lane mapping, 32-bit row offsets.

constexpr int H = 64;

__device__ int   g_idx_is64;
__device__ float g_relD[4 * H];   // rel[r+1][h] - rel[0][h]

__global__ void prep_kernel(const float* __restrict__ rel_emb,
                            const void* __restrict__ edge_idx) {
    const int t = threadIdx.x;
    if (t < 4 * H) {
        const int r = t >> 6, h = t & 63;
        g_relD[t] = rel_emb[(r + 1) * H + h] - rel_emb[h];
    }
    if (t == 0) {
        // int64-vs-int32 index detection: true int64 indices are all in
        // [0, 50000). int32 data reinterpreted as int64 gives lo + hi*2^32
        // with hi ~ U[0,50000): passing all 8 checks is ~impossible.
        const long long* p = (const long long*)edge_idx;
        int is64 = 1;
        #pragma unroll
        for (int i = 0; i < 8; i++) {
            long long v = p[i];
            if (v < 0 || v >= 50000) is64 = 0;
        }
        g_idx_is64 = is64;
    }
}

__device__ __forceinline__ float softmax_expect(const float sc[4]) {
    // score'[0] = 0, score'[r+1] = sc[r]
    float m = 0.f;
    #pragma unroll
    for (int r = 0; r < 4; r++) m = fmaxf(m, sc[r]);
    float den = __expf(-m);     // label-0 term
    float num = 0.f;
    #pragma unroll
    for (int r = 0; r < 4; r++) {
        const float ex = __expf(sc[r] - m);
        den += ex;
        num = fmaf(ex, (float)(r + 1), num);
    }
    return num / den;
}

__global__ __launch_bounds__(256, 5) void edge_decoder_kernel(
    const float* __restrict__ z_user,
    const float* __restrict__ z_movie,
    const void* __restrict__ edge_idx,
    float* __restrict__ out,
    int E)
{
    __shared__ float s_rel[4 * H];
    for (int t = threadIdx.x; t < 4 * H; t += 256)
        s_rel[t] = g_relD[t];
    __syncthreads();

    const int tid     = blockIdx.x * blockDim.x + threadIdx.x;
    const int sub     = threadIdx.x & 7;                 // lane within 8-lane group
    const int ngroups = (gridDim.x * blockDim.x) >> 3;   // total edge groups
    const int g0      = tid >> 3;

    const int is64 = g_idx_is64;
    const long long* p64 = (const long long*)edge_idx;
    const int*       p32 = (const int*)edge_idx;

    const float* rel_lo = s_rel + 4 * sub;        // floats [4sub..4sub+3]
    const float* rel_hi = s_rel + 32 + 4 * sub;   // floats [32+4sub..+3]

    for (int e = g0; e < E; e += 2 * ngroups) {
        const int  e2   = e + ngroups;
        const bool has2 = (e2 < E);

        // ---- issue ALL loads up front: 2 index pairs, then 8 gather float4s
        int sA, dA, sB = 0, dB = 0;
        if (is64) {
            sA = (int)__ldg(p64 + e);
            dA = (int)__ldg(p64 + (long long)E + e);
            if (has2) { sB = (int)__ldg(p64 + e2); dB = (int)__ldg(p64 + (long long)E + e2); }
        } else {
            sA = __ldg(p32 + e);
            dA = __ldg(p32 + E + e);
            if (has2) { sB = __ldg(p32 + e2); dB = __ldg(p32 + E + e2); }
        }

        const float* uA = z_user  + sA * H;
        const float* mA = z_movie + dA * H;
        const float* uB = z_user  + sB * H;   // idx 0 when !has2 (safe)
        const float* mB = z_movie + dB * H;

        const float4 zsA0 = *reinterpret_cast<const float4*>(uA + 4 * sub);
        const float4 zdA0 = *reinterpret_cast<const float4*>(mA + 4 * sub);
        const float4 zsA1 = *reinterpret_cast<const float4*>(uA + 32 + 4 * sub);
        const float4 zdA1 = *reinterpret_cast<const float4*>(mA + 32 + 4 * sub);
        const float4 zsB0 = *reinterpret_cast<const float4*>(uB + 4 * sub);
        const float4 zdB0 = *reinterpret_cast<const float4*>(mB + 4 * sub);
        const float4 zsB1 = *reinterpret_cast<const float4*>(uB + 32 + 4 * sub);
        const float4 zdB1 = *reinterpret_cast<const float4*>(mB + 32 + 4 * sub);

        // ---- elementwise products
        const float a0 = zsA0.x * zdA0.x, a1 = zsA0.y * zdA0.y,
                    a2 = zsA0.z * zdA0.z, a3 = zsA0.w * zdA0.w;
        const float a4 = zsA1.x * zdA1.x, a5 = zsA1.y * zdA1.y,
                    a6 = zsA1.z * zdA1.z, a7 = zsA1.w * zdA1.w;
        const float b0 = zsB0.x * zdB0.x, b1 = zsB0.y * zdB0.y,
                    b2 = zsB0.z * zdB0.z, b3 = zsB0.w * zdB0.w;
        const float b4 = zsB1.x * zdB1.x, b5 = zsB1.y * zdB1.y,
                    b6 = zsB1.z * zdB1.z, b7 = zsB1.w * zdB1.w;

        // ---- scores: relD read from smem with short liveness, shared by A & B
        float scA[4], scB[4];
        #pragma unroll
        for (int r = 0; r < 4; r++) {
            const float4 r0 = *reinterpret_cast<const float4*>(rel_lo + r * H);
            const float4 r1 = *reinterpret_cast<const float4*>(rel_hi + r * H);
            scA[r] = fmaf(a0, r0.x, fmaf(a1, r0.y, fmaf(a2, r0.z, a3 * r0.w)))
                   + fmaf(a4, r1.x, fmaf(a5, r1.y, fmaf(a6, r1.z, a7 * r1.w)));
            scB[r] = fmaf(b0, r0.x, fmaf(b1, r0.y, fmaf(b2, r0.z, b3 * r0.w)))
                   + fmaf(b4, r1.x, fmaf(b5, r1.y, fmaf(b6, r1.z, b7 * r1.w)));
        }

        // ---- butterfly reduce across the 8-lane group
        #pragma unroll
        for (int off = 4; off >= 1; off >>= 1) {
            #pragma unroll
            for (int r = 0; r < 4; r++) {
                scA[r] += __shfl_xor_sync(0xffffffffu, scA[r], off);
                scB[r] += __shfl_xor_sync(0xffffffffu, scB[r], off);
            }
        }

        if (sub == 0) {
            out[e] = softmax_expect(scA);
            if (has2) out[e2] = softmax_expect(scB);
        }
    }
}

extern "C" void kernel_launch(void* const* d_in, const int* in_sizes, int n_in,
                              void* d_out, int out_size) {
    const float* z_user  = (const float*)d_in[0];
    const float* z_movie = (const float*)d_in[1];
    const float* rel_emb = (const float*)d_in[2];
    const void*  eidx    = d_in[3];
    float* out = (float*)d_out;

    const int E = out_size;  // one rating per edge

    prep_kernel<<<1, 256>>>(rel_emb, eidx);

    // SINGLE WAVE: exactly 5 CTAs/SM x 152 SMs. Each 8-lane group strides
    // through ~41 edges.
    const int threads = 256;
    const int blocks  = 152 * 5;
    edge_decoder_kernel<<<blocks, threads>>>(z_user, z_movie, eidx, out, E);
}

// round 9
// speedup vs baseline: 1.1713x; 1.1713x over previous
#include <cuda_runtime.h>
#include <cuda_bf16.h>

// EdgeDecoder: per-edge bilinear scores over 5 relations + softmax-expected rating.
//   z_user  [100000, 64] f32
//   z_movie [ 50000, 64] f32
//   rel_emb [     5, 64] f32
//   edge_label_index [2, E] int (32 or 64 — detected at runtime)
//   out [E] f32
//
// R9 = R7 (best grid: 1216 CTAs) + VALUE-SPLITTING BUTTERFLY REDUCE:
//   The old reduce shuffled all 8 score partials (2 edges x 4 rels) at every
//   stage: 24 SHFL / iteration. SHFL rides the MIO/LSU path (the ~69%-busy
//   resource). New scheme halves the live value count each stage via SELs
//   (idle ALU pipe): xor4->4 shfl, xor2->2, xor1->1, ending with lane r
//   holding total scA_r and lane 4+r holding scB_r; a 4-shfl gather feeds
//   lanes 0 and 4 which run ONE shared softmax for both edges.
//   SHFL 24 -> 11 per 2 edges; softmax executions halved.
// Retained: smem relD + softmax shift trick, 2-edge unroll, line-aligned
// lane mapping, 32-bit row offsets, 1216-block grid (R8 single-wave reverted).

constexpr int H = 64;

__device__ int   g_idx_is64;
__device__ float g_relD[4 * H];   // rel[r+1][h] - rel[0][h]

__global__ void prep_kernel(const float* __restrict__ rel_emb,
                            const void* __restrict__ edge_idx) {
    const int t = threadIdx.x;
    if (t < 4 * H) {
        const int r = t >> 6, h = t & 63;
        g_relD[t] = rel_emb[(r + 1) * H + h] - rel_emb[h];
    }
    if (t == 0) {
        // int64-vs-int32 index detection: true int64 indices are all in
        // [0, 50000). int32 data reinterpreted as int64 gives lo + hi*2^32
        // with hi ~ U[0,50000): passing all 8 checks is ~impossible.
        const long long* p = (const long long*)edge_idx;
        int is64 = 1;
        #pragma unroll
        for (int i = 0; i < 8; i++) {
            long long v = p[i];
            if (v < 0 || v >= 50000) is64 = 0;
        }
        g_idx_is64 = is64;
    }
}

__device__ __forceinline__ float softmax_expect4(float s0, float s1, float s2, float s3) {
    // score'[0] = 0, score'[r+1] = s_r
    float m = fmaxf(fmaxf(s0, s1), fmaxf(s2, s3));
    m = fmaxf(m, 0.f);
    const float e0 = __expf(s0 - m);
    const float e1 = __expf(s1 - m);
    const float e2 = __expf(s2 - m);
    const float e3 = __expf(s3 - m);
    const float den = __expf(-m) + e0 + e1 + e2 + e3;
    const float num = fmaf(e3, 4.f, fmaf(e2, 3.f, fmaf(e1, 2.f, e0)));
    return num / den;
}

__global__ __launch_bounds__(256) void edge_decoder_kernel(
    const float* __restrict__ z_user,
    const float* __restrict__ z_movie,
    const void* __restrict__ edge_idx,
    float* __restrict__ out,
    int E)
{
    __shared__ float s_rel[4 * H];
    for (int t = threadIdx.x; t < 4 * H; t += 256)
        s_rel[t] = g_relD[t];
    __syncthreads();

    const int tid     = blockIdx.x * blockDim.x + threadIdx.x;
    const int sub     = threadIdx.x & 7;                 // lane within 8-lane group
    const int ngroups = (gridDim.x * blockDim.x) >> 3;   // total edge groups
    const int g0      = tid >> 3;
    const int lane    = threadIdx.x & 31;
    const int gbase   = lane & ~7;                       // group base lane in warp

    const int is64 = g_idx_is64;
    const long long* p64 = (const long long*)edge_idx;
    const int*       p32 = (const int*)edge_idx;

    const float* rel_lo = s_rel + 4 * sub;        // floats [4sub..4sub+3]
    const float* rel_hi = s_rel + 32 + 4 * sub;   // floats [32+4sub..+3]

    for (int e = g0; e < E; e += 2 * ngroups) {
        const int  e2   = e + ngroups;
        const bool has2 = (e2 < E);

        // ---- issue ALL loads up front: 2 index pairs, then 8 gather float4s
        int sA, dA, sB = 0, dB = 0;
        if (is64) {
            sA = (int)__ldg(p64 + e);
            dA = (int)__ldg(p64 + (long long)E + e);
            if (has2) { sB = (int)__ldg(p64 + e2); dB = (int)__ldg(p64 + (long long)E + e2); }
        } else {
            sA = __ldg(p32 + e);
            dA = __ldg(p32 + E + e);
            if (has2) { sB = __ldg(p32 + e2); dB = __ldg(p32 + E + e2); }
        }

        const float* uA = z_user  + sA * H;
        const float* mA = z_movie + dA * H;
        const float* uB = z_user  + sB * H;   // idx 0 when !has2 (safe)
        const float* mB = z_movie + dB * H;

        const float4 zsA0 = *reinterpret_cast<const float4*>(uA + 4 * sub);
        const float4 zdA0 = *reinterpret_cast<const float4*>(mA + 4 * sub);
        const float4 zsA1 = *reinterpret_cast<const float4*>(uA + 32 + 4 * sub);
        const float4 zdA1 = *reinterpret_cast<const float4*>(mA + 32 + 4 * sub);
        const float4 zsB0 = *reinterpret_cast<const float4*>(uB + 4 * sub);
        const float4 zdB0 = *reinterpret_cast<const float4*>(mB + 4 * sub);
        const float4 zsB1 = *reinterpret_cast<const float4*>(uB + 32 + 4 * sub);
        const float4 zdB1 = *reinterpret_cast<const float4*>(mB + 32 + 4 * sub);

        // ---- elementwise products
        const float a0 = zsA0.x * zdA0.x, a1 = zsA0.y * zdA0.y,
                    a2 = zsA0.z * zdA0.z, a3 = zsA0.w * zdA0.w;
        const float a4 = zsA1.x * zdA1.x, a5 = zsA1.y * zdA1.y,
                    a6 = zsA1.z * zdA1.z, a7 = zsA1.w * zdA1.w;
        const float b0 = zsB0.x * zdB0.x, b1 = zsB0.y * zdB0.y,
                    b2 = zsB0.z * zdB0.z, b3 = zsB0.w * zdB0.w;
        const float b4 = zsB1.x * zdB1.x, b5 = zsB1.y * zdB1.y,
                    b6 = zsB1.z * zdB1.z, b7 = zsB1.w * zdB1.w;

        // ---- per-lane score partials (relD from smem, shared by A & B)
        float x[8];   // x[0..3]=scA_r, x[4..7]=scB_r
        #pragma unroll
        for (int r = 0; r < 4; r++) {
            const float4 r0 = *reinterpret_cast<const float4*>(rel_lo + r * H);
            const float4 r1 = *reinterpret_cast<const float4*>(rel_hi + r * H);
            x[r]     = fmaf(a0, r0.x, fmaf(a1, r0.y, fmaf(a2, r0.z, a3 * r0.w)))
                     + fmaf(a4, r1.x, fmaf(a5, r1.y, fmaf(a6, r1.z, a7 * r1.w)));
            x[4 + r] = fmaf(b0, r0.x, fmaf(b1, r0.y, fmaf(b2, r0.z, b3 * r0.w)))
                     + fmaf(b4, r1.x, fmaf(b5, r1.y, fmaf(b6, r1.z, b7 * r1.w)));
        }

        // ---- value-splitting butterfly reduce (8 values over 8 lanes)
        // stage xor4: lanes 0-3 keep A, lanes 4-7 keep B
        const bool hi4 = (sub & 4) != 0;
        float k4[4];
        #pragma unroll
        for (int i = 0; i < 4; i++) {
            const float keep = hi4 ? x[4 + i] : x[i];
            const float give = hi4 ? x[i]     : x[4 + i];
            k4[i] = keep + __shfl_xor_sync(0xffffffffu, give, 4);
        }
        // stage xor2: keep values {0,1} on low pair, {2,3} on high pair
        const bool hi2 = (sub & 2) != 0;
        float k2[2];
        {
            const float kp0 = hi2 ? k4[2] : k4[0];
            const float gv0 = hi2 ? k4[0] : k4[2];
            const float kp1 = hi2 ? k4[3] : k4[1];
            const float gv1 = hi2 ? k4[1] : k4[3];
            k2[0] = kp0 + __shfl_xor_sync(0xffffffffu, gv0, 2);
            k2[1] = kp1 + __shfl_xor_sync(0xffffffffu, gv1, 2);
        }
        // stage xor1
        const bool hi1 = (sub & 1) != 0;
        const float kp = hi1 ? k2[1] : k2[0];
        const float gv = hi1 ? k2[0] : k2[1];
        const float tot = kp + __shfl_xor_sync(0xffffffffu, gv, 1);
        // now: lane gbase+r holds scA_r total; lane gbase+4+r holds scB_r total

        // ---- gather each half's 4 totals (lanes 0-3 get A, 4-7 get B)
        const int src = gbase + (sub & 4);
        const float v0 = __shfl_sync(0xffffffffu, tot, src + 0);
        const float v1 = __shfl_sync(0xffffffffu, tot, src + 1);
        const float v2 = __shfl_sync(0xffffffffu, tot, src + 2);
        const float v3 = __shfl_sync(0xffffffffu, tot, src + 3);

        // ---- one shared softmax execution covers both edges
        if ((sub & 3) == 0) {
            const float r = softmax_expect4(v0, v1, v2, v3);
            if (sub == 0)       out[e]  = r;
            else if (has2)      out[e2] = r;
        }
    }
}

extern "C" void kernel_launch(void* const* d_in, const int* in_sizes, int n_in,
                              void* d_out, int out_size) {
    const float* z_user  = (const float*)d_in[0];
    const float* z_movie = (const float*)d_in[1];
    const float* rel_emb = (const float*)d_in[2];
    const void*  eidx    = d_in[3];
    float* out = (float*)d_out;

    const int E = out_size;  // one rating per edge

    prep_kernel<<<1, 256>>>(rel_emb, eidx);

    // 1216 CTAs (R7 best): 1.6 waves backfill per-CTA latency spread better
    // than a single long wave (R8 regression).
    const int threads = 256;
    const int blocks  = 152 * 8;
    edge_decoder_kernel<<<blocks, threads>>>(z_user, z_movie, eidx, out, E);
}